// round 3
// baseline (speedup 1.0000x reference)
#include <cuda_runtime.h>

// Model_35347580846430: reflect-pad depthwise moving average, W=25, PAD=12
// x: [B=64, T=4096, N=128] f32, out same shape.
// out[b,t,n] = mean_{k=-12..12} x[b, reflect(t+k), n]
//
// R3: CHUNK 64 -> 256. Cuts halo read-amp 1.375 -> 1.09 AND shrinks the
// resident-warp count to 2048 so the sliding-window outgoing re-read's reuse
// distance (25 iters * 768 B * 2048 warps ~= 39 MB) fits in L2 (126 MB),
// eliminating outgoing-read DRAM leakage. Single fully-resident wave.

#define B_DIM 64
#define T_DIM 4096
#define N_DIM 128
#define PAD   12
#define WIN   25
#define CHUNK 256         // t-steps per thread
#define TY    2           // chunks per block (blockDim.y)

// N as float2: 64 lanes (2 warps) cover one row
#define N2 (N_DIM / 2)

__device__ __forceinline__ int reflect_idx(int t) {
    // np.pad 'reflect': x[-1] -> x[1], x[T] -> x[T-2]
    t = (t < 0) ? -t : t;
    t = (t >= T_DIM) ? (2 * (T_DIM - 1) - t) : t;
    return t;
}

__global__ __launch_bounds__(64 * TY)
void ma25_kernel(const float2* __restrict__ x, float2* __restrict__ out) {
    const int tx    = threadIdx.x;                       // 0..63 -> float2 group over N
    const int chunk = blockIdx.x * TY + threadIdx.y;     // which t-chunk
    const int b     = blockIdx.y;
    const int t0    = chunk * CHUNK;

    const float2* __restrict__ xb = x   + (size_t)b * T_DIM * N2 + tx;
    float2*       __restrict__ ob = out + (size_t)b * T_DIM * N2 + tx;

    // Initial window sum centered at t0: t in [t0-12, t0+12]
    float sx = 0.f, sy = 0.f;
    #pragma unroll
    for (int k = -PAD; k <= PAD; k++) {
        int t = reflect_idx(t0 + k);
        float2 v = xb[(size_t)t * N2];
        sx += v.x; sy += v.y;
    }

    const float inv = 1.0f / (float)WIN;
    {
        float2 o; o.x = sx * inv; o.y = sy * inv;
        ob[(size_t)t0 * N2] = o;
    }

    // Slide the window across the rest of the chunk.
    #pragma unroll 8
    for (int i = 1; i < CHUNK; i++) {
        const int t = t0 + i;
        int tin  = t + PAD;      if (tin  >= T_DIM) tin  = 2 * (T_DIM - 1) - tin;
        int tout = t - PAD - 1;  if (tout < 0)      tout = -tout;

        float2 a = xb[(size_t)tin  * N2];
        float2 d = xb[(size_t)tout * N2];
        sx += a.x - d.x;
        sy += a.y - d.y;

        float2 o; o.x = sx * inv; o.y = sy * inv;
        ob[(size_t)t * N2] = o;
    }
}

extern "C" void kernel_launch(void* const* d_in, const int* in_sizes, int n_in,
                              void* d_out, int out_size) {
    const float2* x = (const float2*)d_in[0];
    float2* out = (float2*)d_out;

    dim3 block(64, TY);                            // 128 threads, 4 warps
    dim3 grid(T_DIM / CHUNK / TY, B_DIM);          // (8, 64) = 512 blocks
    ma25_kernel<<<grid, block>>>(x, out);
}

// round 4
// speedup vs baseline: 1.2450x; 1.2450x over previous
#include <cuda_runtime.h>

// Model_35347580846430: reflect-pad depthwise moving average, W=25, PAD=12
// x: [B=64, T=4096, N=128] f32, out same shape.
// out[b,t,n] = mean_{k=-12..12} x[b, reflect(t+k), n]
//
// R4: CHUNK=128 (read-amp 1.195, outgoing-reuse 78MB < L2) with 4096 warps
// (proven ~6 TB/s), plus explicit 8-wide load batching to raise per-warp MLP
// (R3 showed regs=32 strangled the load reorder window at low occupancy).

#define B_DIM 64
#define T_DIM 4096
#define N_DIM 128
#define PAD   12
#define WIN   25
#define CHUNK 128         // t-steps per thread
#define TY    4           // chunks per block (blockDim.y)
#define BATCH 8           // software-pipeline width

// N as float2: 64 lanes (2 warps) cover one row
#define N2 (N_DIM / 2)

__device__ __forceinline__ int reflect_idx(int t) {
    // np.pad 'reflect': x[-1] -> x[1], x[T] -> x[T-2]
    t = (t < 0) ? -t : t;
    t = (t >= T_DIM) ? (2 * (T_DIM - 1) - t) : t;
    return t;
}

__global__ __launch_bounds__(64 * TY)
void ma25_kernel(const float2* __restrict__ x, float2* __restrict__ out) {
    const int tx    = threadIdx.x;                       // 0..63 -> float2 group over N
    const int chunk = blockIdx.x * TY + threadIdx.y;     // which t-chunk
    const int b     = blockIdx.y;
    const int t0    = chunk * CHUNK;

    const float2* __restrict__ xb = x   + (size_t)b * T_DIM * N2 + tx;
    float2*       __restrict__ ob = out + (size_t)b * T_DIM * N2 + tx;

    // Window sum centered at t0-1: t in [t0-13, t0+11].
    // Then the steady loop produces outputs for i = 0..CHUNK-1 uniformly.
    float sx = 0.f, sy = 0.f;
    #pragma unroll
    for (int k = -PAD - 1; k <= PAD - 1; k++) {
        int t = reflect_idx(t0 + k);
        float2 v = xb[(size_t)t * N2];
        sx += v.x; sy += v.y;
    }

    const float inv = 1.0f / (float)WIN;

    for (int i0 = 0; i0 < CHUNK; i0 += BATCH) {
        // Phase 1: batch 2*BATCH independent loads (front-batched LDGs).
        float2 a[BATCH], d[BATCH];
        #pragma unroll
        for (int j = 0; j < BATCH; j++) {
            const int t = t0 + i0 + j;
            int tin  = t + PAD;      if (tin  >= T_DIM) tin  = 2 * (T_DIM - 1) - tin;
            int tout = t - PAD - 1;  if (tout < 0)      tout = -tout;
            a[j] = xb[(size_t)tin  * N2];
            d[j] = xb[(size_t)tout * N2];
        }
        // Phase 2: serial sum chain + stores.
        #pragma unroll
        for (int j = 0; j < BATCH; j++) {
            sx += a[j].x - d[j].x;
            sy += a[j].y - d[j].y;
            float2 o; o.x = sx * inv; o.y = sy * inv;
            ob[(size_t)(t0 + i0 + j) * N2] = o;
        }
    }
}

extern "C" void kernel_launch(void* const* d_in, const int* in_sizes, int n_in,
                              void* d_out, int out_size) {
    const float2* x = (const float2*)d_in[0];
    float2* out = (float2*)d_out;

    dim3 block(64, TY);                            // 256 threads, 8 warps
    dim3 grid(T_DIM / CHUNK / TY, B_DIM);          // (8, 64) = 512 blocks
    ma25_kernel<<<grid, block>>>(x, out);
}

// round 5
// speedup vs baseline: 1.2669x; 1.0176x over previous
#include <cuda_runtime.h>

// Model_35347580846430: reflect-pad depthwise moving average, W=25, PAD=12
// x: [B=64, T=4096, N=128] f32, out same shape.
// out[b,t,n] = mean_{k=-12..12} x[b, reflect(t+k), n]
//
// R5: scalar-float lanes, 128 lanes (4 warps) per (b,chunk) row -> 8192 warps
// (the proven 6.1+ TB/s regime) while KEEPING CHUNK=128 (read amp 1.195,
// ~294 MB total traffic). Scalar lanes also shrink the BATCH register set to
// 16 floats so ptxas can truly front-batch 16 independent LDGs (R4's regs=32
// showed the float2 batch got re-serialized).

#define B_DIM 64
#define T_DIM 4096
#define N_DIM 128
#define PAD   12
#define WIN   25
#define CHUNK 128         // t-steps per thread
#define CY    2           // chunks per block (blockDim.y)
#define BATCH 8           // software-pipeline width

__device__ __forceinline__ int reflect_idx(int t) {
    // np.pad 'reflect': x[-1] -> x[1], x[T] -> x[T-2]
    t = (t < 0) ? -t : t;
    t = (t >= T_DIM) ? (2 * (T_DIM - 1) - t) : t;
    return t;
}

__global__ __launch_bounds__(N_DIM * CY)
void ma25_kernel(const float* __restrict__ x, float* __restrict__ out) {
    const int n     = threadIdx.x;                       // 0..127 -> feature
    const int chunk = blockIdx.x * CY + threadIdx.y;     // which t-chunk
    const int b     = blockIdx.y;
    const int t0    = chunk * CHUNK;

    const float* __restrict__ xb = x   + (size_t)b * T_DIM * N_DIM + n;
    float*       __restrict__ ob = out + (size_t)b * T_DIM * N_DIM + n;

    // Window sum centered at t0-1: t in [t0-13, t0+11].
    // Steady loop then produces outputs for i = 0..CHUNK-1 uniformly.
    float s = 0.f;
    #pragma unroll
    for (int k = -PAD - 1; k <= PAD - 1; k++) {
        int t = reflect_idx(t0 + k);
        s += xb[(size_t)t * N_DIM];
    }

    const float inv = 1.0f / (float)WIN;

    for (int i0 = 0; i0 < CHUNK; i0 += BATCH) {
        // Phase 1: 2*BATCH independent loads, front-batched.
        float a[BATCH], d[BATCH];
        #pragma unroll
        for (int j = 0; j < BATCH; j++) {
            const int t = t0 + i0 + j;
            int tin  = t + PAD;      if (tin  >= T_DIM) tin  = 2 * (T_DIM - 1) - tin;
            int tout = t - PAD - 1;  if (tout < 0)      tout = -tout;
            a[j] = xb[(size_t)tin  * N_DIM];
            d[j] = xb[(size_t)tout * N_DIM];
        }
        // Phase 2: serial sum chain + stores.
        #pragma unroll
        for (int j = 0; j < BATCH; j++) {
            s += a[j] - d[j];
            ob[(size_t)(t0 + i0 + j) * N_DIM] = s * inv;
        }
    }
}

extern "C" void kernel_launch(void* const* d_in, const int* in_sizes, int n_in,
                              void* d_out, int out_size) {
    const float* x = (const float*)d_in[0];
    float* out = (float*)d_out;

    dim3 block(N_DIM, CY);                         // 256 threads, 8 warps
    dim3 grid(T_DIM / CHUNK / CY, B_DIM);          // (16, 64) = 1024 blocks
    ma25_kernel<<<grid, block>>>(x, out);
}